// round 7
// baseline (speedup 1.0000x reference)
#include <cuda_runtime.h>
#include <cstdint>

#define C_DIM 272
#define T_DIM 1024
#define BATCH 128
#define MT 64
#define NT 256
#define PITCH 20

__device__ int g_sidx[BATCH];
__device__ int g_flag;   // 1 => mma result bad -> run SIMT fallback

__global__ void decode_sidx_kernel(const int* __restrict__ raw) {
    __shared__ int is_i32;
    if (threadIdx.x == 0) { is_i32 = 0; g_flag = 0; }
    __syncthreads();
    int t = threadIdx.x;
    if (t < 64 && raw[2 * t + 1] != 0) atomicExch(&is_i32, 1);
    __syncthreads();
    if (t < BATCH) g_sidx[t] = is_i32 ? raw[t] : raw[2 * t];
}

__device__ __forceinline__ uint32_t tf32c(float a) {
    uint32_t u; asm("cvt.rna.tf32.f32 %0, %1;" : "=r"(u) : "f"(a)); return u;
}
__device__ __forceinline__ void mma8(float* d, const uint32_t* a, uint32_t b0, uint32_t b1) {
    asm volatile("mma.sync.aligned.m16n8k8.row.col.f32.tf32.tf32.f32 "
        "{%0,%1,%2,%3}, {%4,%5,%6,%7}, {%8,%9}, {%0,%1,%2,%3};"
        : "+f"(d[0]), "+f"(d[1]), "+f"(d[2]), "+f"(d[3])
        : "r"(a[0]), "r"(a[1]), "r"(a[2]), "r"(a[3]), "r"(b0), "r"(b1));
}

// CTA: 64(chan) x 256(time); 8 warps (2x4), warp tile 32x64; tf32 x2 (A split).
__global__ __launch_bounds__(256, 2)
void mma_gemm_kernel(const float* __restrict__ x, const float* __restrict__ W,
                     float* __restrict__ out) {
    __shared__ float As[MT][PITCH];   // [c][k], k row of 16 + pad
    __shared__ float Bs[NT][PITCH];   // [t][k] (x transposed in-CTA)

    const int b = blockIdx.z, oBase = blockIdx.y * MT, tBase = blockIdx.x * NT;
    const int s = g_sidx[b];
    const float* __restrict__ Wb = W + (size_t)s * C_DIM * C_DIM;
    const float* __restrict__ xb = x + (size_t)b * C_DIM * T_DIM;

    const int tid = threadIdx.x, lane = tid & 31, warp = tid >> 5;
    const int wm = (warp >> 2) * 32, wn = (warp & 3) * 64;
    const int fr = lane >> 2, fc = lane & 3;   // fragment row/col within atoms

    const int aRow = tid >> 2, aK = (tid & 3) * 4;
    const bool aV = (oBase + aRow) < C_DIM;
    const float* aP = Wb + (size_t)(oBase + aRow) * C_DIM + aK;

    float acc[2][8][4];
#pragma unroll
    for (int mb = 0; mb < 2; mb++)
#pragma unroll
        for (int nb = 0; nb < 8; nb++)
#pragma unroll
            for (int j = 0; j < 4; j++) acc[mb][nb][j] = 0.0f;

    for (int k0 = 0; k0 < C_DIM; k0 += 16) {   // 272 = 17*16 exact
        const float4 av = aV ? *(const float4*)(aP + k0)
                             : make_float4(0.f, 0.f, 0.f, 0.f);
        *(float4*)&As[aRow][aK] = av;
#pragma unroll
        for (int i = 0; i < 16; i++)
            Bs[tid][i] = xb[(size_t)(k0 + i) * T_DIM + tBase + tid];
        __syncthreads();

#pragma unroll
        for (int ks = 0; ks < 16; ks += 8) {
            uint32_t ab[2][4], asm_[2][4];
#pragma unroll
            for (int mb = 0; mb < 2; mb++) {
                const int r = wm + mb * 16 + fr;
                const int c = ks + fc;
                const float v0 = As[r][c], v1 = As[r + 8][c];
                const float v2 = As[r][c + 4], v3 = As[r + 8][c + 4];
                ab[mb][0] = tf32c(v0); asm_[mb][0] = tf32c(v0 - __uint_as_float(ab[mb][0]));
                ab[mb][1] = tf32c(v1); asm_[mb][1] = tf32c(v1 - __uint_as_float(ab[mb][1]));
                ab[mb][2] = tf32c(v2); asm_[mb][2] = tf32c(v2 - __uint_as_float(ab[mb][2]));
                ab[mb][3] = tf32c(v3); asm_[mb][3] = tf32c(v3 - __uint_as_float(ab[mb][3]));
            }
#pragma unroll
            for (int nb = 0; nb < 8; nb++) {
                const int n = wn + nb * 8 + fr;
                const uint32_t b0 = tf32c(Bs[n][ks + fc]);
                const uint32_t b1 = tf32c(Bs[n][ks + 4 + fc]);
                mma8(acc[0][nb], ab[0], b0, b1);
                mma8(acc[0][nb], asm_[0], b0, b1);
                mma8(acc[1][nb], ab[1], b0, b1);
                mma8(acc[1][nb], asm_[1], b0, b1);
            }
        }
        __syncthreads();
    }

    float* __restrict__ ob = out + (size_t)b * C_DIM * T_DIM;
#pragma unroll
    for (int mb = 0; mb < 2; mb++) {
        const int r0 = oBase + wm + mb * 16 + fr;
        const int r1 = r0 + 8;
#pragma unroll
        for (int nb = 0; nb < 8; nb++) {
            const int cc = tBase + wn + nb * 8 + fc * 2;
            if (r0 < C_DIM)
                *(float2*)&ob[(size_t)r0 * T_DIM + cc] =
                    make_float2(acc[mb][nb][0], acc[mb][nb][1]);
            if (r1 < C_DIM)
                *(float2*)&ob[(size_t)r1 * T_DIM + cc] =
                    make_float2(acc[mb][nb][2], acc[mb][nb][3]);
        }
    }
}

// Sample 4096 outputs, recompute fp32, flag if any off by > 3e-3 rel.
__global__ void check_kernel(const float* __restrict__ x, const float* __restrict__ W,
                             const float* __restrict__ out) {
    const int i = blockIdx.x * blockDim.x + threadIdx.x;
    const int b = i & (BATCH - 1);
    const int c = (i * 37) % C_DIM;
    const int t = (i * 613) % T_DIM;
    const float* wr = W + ((size_t)g_sidx[b] * C_DIM + c) * C_DIM;
    const float* xc = x + (size_t)b * C_DIM * T_DIM + t;
    float acc = 0.f;
    for (int k = 0; k < C_DIM; k++) acc += wr[k] * xc[(size_t)k * T_DIM];
    const float got = out[((size_t)b * C_DIM + c) * T_DIM + t];
    if (fabsf(got - acc) > 3e-3f * fmaxf(fabsf(acc), 1.0f)) atomicExch(&g_flag, 1);
}

// Proven SIMT fallback (633us path); early-exits unless flagged.
__global__ __launch_bounds__(256)
void simt_gemm_kernel(const float* __restrict__ x, const float* __restrict__ W,
                      float* __restrict__ out) {
    if (!g_flag) return;
    __shared__ float As[64][17];
    __shared__ float Bs[16][64];
    const int b = blockIdx.z, oBase = blockIdx.y * 64, tBase = blockIdx.x * 64;
    const float* __restrict__ Wb = W + (size_t)g_sidx[b] * C_DIM * C_DIM;
    const float* __restrict__ xb = x + (size_t)b * C_DIM * T_DIM;
    float* __restrict__ ob = out + (size_t)b * C_DIM * T_DIM;
    const int tid = threadIdx.x, tx = tid & 15, ty = tid >> 4;
    const int aRow = tid >> 2, aCol = (tid & 3) * 4, bRow = tid >> 4, bCol = (tid & 15) * 4;
    const int oLoad = oBase + aRow;
    const bool aValid = (oLoad < C_DIM);
    const float* aPtr = Wb + (size_t)oLoad * C_DIM + aCol;
    const float* bPtr = xb + (size_t)bRow * T_DIM + tBase + bCol;
    float acc[4][4] = {};
    for (int k0 = 0; k0 < C_DIM; k0 += 16) {
        float4 av = aValid ? *(const float4*)(aPtr + k0) : make_float4(0.f,0.f,0.f,0.f);
        float4 bv = *(const float4*)(bPtr + (size_t)k0 * T_DIM);
        As[aRow][aCol+0]=av.x; As[aRow][aCol+1]=av.y; As[aRow][aCol+2]=av.z; As[aRow][aCol+3]=av.w;
        *(float4*)&Bs[bRow][bCol] = bv;
        __syncthreads();
#pragma unroll
        for (int k = 0; k < 16; k++) {
            const float a0=As[ty*4+0][k], a1=As[ty*4+1][k], a2=As[ty*4+2][k], a3=As[ty*4+3][k];
            const float4 bq = *(const float4*)&Bs[k][tx*4];
            acc[0][0]+=a0*bq.x; acc[0][1]+=a0*bq.y; acc[0][2]+=a0*bq.z; acc[0][3]+=a0*bq.w;
            acc[1][0]+=a1*bq.x; acc[1][1]+=a1*bq.y; acc[1][2]+=a1*bq.z; acc[1][3]+=a1*bq.w;
            acc[2][0]+=a2*bq.x; acc[2][1]+=a2*bq.y; acc[2][2]+=a2*bq.z; acc[2][3]+=a2*bq.w;
            acc[3][0]+=a3*bq.x; acc[3][1]+=a3*bq.y; acc[3][2]+=a3*bq.z; acc[3][3]+=a3*bq.w;
        }
        __syncthreads();
    }
#pragma unroll
    for (int i = 0; i < 4; i++) {
        const int oo = oBase + ty * 4 + i;
        if (oo < C_DIM)
            *(float4*)&ob[(size_t)oo * T_DIM + tBase + tx * 4] =
                make_float4(acc[i][0], acc[i][1], acc[i][2], acc[i][3]);
    }
}

extern "C" void kernel_launch(void* const* d_in, const int* in_sizes, int n_in,
                              void* d_out, int out_size) {
    const float* x = (const float*)d_in[0];
    const int* idx = (const int*)d_in[1];
    const float* W = (const float*)d_in[2];
    float* out = (float*)d_out;

    decode_sidx_kernel<<<1, 128>>>(idx);
    dim3 grid(T_DIM / NT, (C_DIM + MT - 1) / MT, BATCH);   // (4, 5, 128)
    mma_gemm_kernel<<<grid, 256>>>(x, W, out);
    check_kernel<<<32, 128>>>(x, W, out);
    dim3 fgrid(16, 5, BATCH);
    simt_gemm_kernel<<<fgrid, 256>>>(x, W, out);
}

// round 8
// speedup vs baseline: 1.8789x; 1.8789x over previous
#include <cuda_runtime.h>
#include <cstdint>

#define C_DIM 272
#define T_DIM 1024
#define BATCH 128
#define MT 64
#define NT 256
#define AP 72
#define TP 264

__device__ int g_sidx[BATCH];
__device__ int g_flag;   // 1 => mma result bad -> run SIMT fallback

__global__ void decode_sidx_kernel(const int* __restrict__ raw) {
    __shared__ int is_i32;
    if (threadIdx.x == 0) { is_i32 = 0; g_flag = 0; }
    __syncthreads();
    int t = threadIdx.x;
    if (t < 64 && raw[2 * t + 1] != 0) atomicExch(&is_i32, 1);
    __syncthreads();
    if (t < BATCH) g_sidx[t] = is_i32 ? raw[t] : raw[2 * t];
}

__device__ __forceinline__ uint32_t tf32c(float a) {
    uint32_t u; asm("cvt.rna.tf32.f32 %0, %1;" : "=r"(u) : "f"(a)); return u;
}
__device__ __forceinline__ void mma8(float* d, const uint32_t* a, uint32_t b0, uint32_t b1) {
    asm volatile("mma.sync.aligned.m16n8k8.row.col.f32.tf32.tf32.f32 "
        "{%0,%1,%2,%3}, {%4,%5,%6,%7}, {%8,%9}, {%0,%1,%2,%3};"
        : "+f"(d[0]), "+f"(d[1]), "+f"(d[2]), "+f"(d[3])
        : "r"(a[0]), "r"(a[1]), "r"(a[2]), "r"(a[3]), "r"(b0), "r"(b1));
}

// CTA: 64(chan) x 256(time); 8 warps (2x4), warp tile 32x64.
// tf32 x3 split; all conversions done at staging, smem holds split tf32.
__global__ __launch_bounds__(256, 2)
void mma_gemm_kernel(const float* __restrict__ x, const float* __restrict__ W,
                     float* __restrict__ out) {
    __shared__ uint32_t AsB[16][AP], AsS[16][AP];    // [k][chan]
    __shared__ uint32_t BsB[16][TP], BsS[16][TP];    // [k][time]

    const int b = blockIdx.z, oBase = blockIdx.y * MT, tBase = blockIdx.x * NT;
    const int s = g_sidx[b];
    const float* __restrict__ Wb = W + (size_t)s * C_DIM * C_DIM;
    const float* __restrict__ xb = x + (size_t)b * C_DIM * T_DIM;

    const int tid = threadIdx.x, lane = tid & 31, warp = tid >> 5;
    const int wm = (warp >> 2) * 32, wn = (warp & 3) * 64;
    const int fr = lane >> 2, fc = lane & 3;

    const int aC = tid & 63, aKq = (tid >> 6) * 4;   // A: row chan, 4 k's
    const bool aV = (oBase + aC) < C_DIM;
    const float* aP = Wb + (size_t)(oBase + aC) * C_DIM + aKq;
    const float* bP = xb + tBase + tid;

    float acc[2][8][4];
#pragma unroll
    for (int mb = 0; mb < 2; mb++)
#pragma unroll
        for (int nb = 0; nb < 8; nb++)
#pragma unroll
            for (int j = 0; j < 4; j++) acc[mb][nb][j] = 0.0f;

    for (int k0 = 0; k0 < C_DIM; k0 += 16) {   // 272 = 17*16 exact
        // ---- stage A (split tf32), [k][c] ----
        const float4 av = aV ? *(const float4*)(aP + k0)
                             : make_float4(0.f, 0.f, 0.f, 0.f);
        {
            const float vv[4] = {av.x, av.y, av.z, av.w};
#pragma unroll
            for (int j = 0; j < 4; j++) {
                const uint32_t big = tf32c(vv[j]);
                AsB[aKq + j][aC] = big;
                AsS[aKq + j][aC] = tf32c(vv[j] - __uint_as_float(big));
            }
        }
        // ---- stage B (split tf32), [k][t], no transpose ----
#pragma unroll
        for (int i = 0; i < 16; i++) {
            const float v = bP[(size_t)(k0 + i) * T_DIM];
            const uint32_t big = tf32c(v);
            BsB[i][tid] = big;
            BsS[i][tid] = tf32c(v - __uint_as_float(big));
        }
        __syncthreads();

#pragma unroll
        for (int ks = 0; ks < 16; ks += 8) {
            uint32_t ab[2][4], al[2][4];
#pragma unroll
            for (int mb = 0; mb < 2; mb++) {
                const int m = wm + mb * 16 + fr;
                ab[mb][0] = AsB[ks + fc][m];     ab[mb][1] = AsB[ks + fc][m + 8];
                ab[mb][2] = AsB[ks + fc + 4][m]; ab[mb][3] = AsB[ks + fc + 4][m + 8];
                al[mb][0] = AsS[ks + fc][m];     al[mb][1] = AsS[ks + fc][m + 8];
                al[mb][2] = AsS[ks + fc + 4][m]; al[mb][3] = AsS[ks + fc + 4][m + 8];
            }
#pragma unroll
            for (int half = 0; half < 2; half++) {
                uint32_t bb[4][2], bl[4][2];
#pragma unroll
                for (int q = 0; q < 4; q++) {
                    const int n = wn + (half * 4 + q) * 8 + fr;
                    bb[q][0] = BsB[ks + fc][n]; bb[q][1] = BsB[ks + fc + 4][n];
                    bl[q][0] = BsS[ks + fc][n]; bl[q][1] = BsS[ks + fc + 4][n];
                }
                // pass 1: Abig*Bbig
#pragma unroll
                for (int q = 0; q < 4; q++) {
                    mma8(acc[0][half * 4 + q], ab[0], bb[q][0], bb[q][1]);
                    mma8(acc[1][half * 4 + q], ab[1], bb[q][0], bb[q][1]);
                }
                // pass 2: Asmall*Bbig
#pragma unroll
                for (int q = 0; q < 4; q++) {
                    mma8(acc[0][half * 4 + q], al[0], bb[q][0], bb[q][1]);
                    mma8(acc[1][half * 4 + q], al[1], bb[q][0], bb[q][1]);
                }
                // pass 3: Abig*Bsmall
#pragma unroll
                for (int q = 0; q < 4; q++) {
                    mma8(acc[0][half * 4 + q], ab[0], bl[q][0], bl[q][1]);
                    mma8(acc[1][half * 4 + q], ab[1], bl[q][0], bl[q][1]);
                }
            }
        }
        __syncthreads();
    }

    float* __restrict__ ob = out + (size_t)b * C_DIM * T_DIM;
#pragma unroll
    for (int mb = 0; mb < 2; mb++) {
        const int r0 = oBase + wm + mb * 16 + fr;
        const int r1 = r0 + 8;
#pragma unroll
        for (int nb = 0; nb < 8; nb++) {
            const int cc = tBase + wn + nb * 8 + fc * 2;
            if (r0 < C_DIM)
                *(float2*)&ob[(size_t)r0 * T_DIM + cc] =
                    make_float2(acc[mb][nb][0], acc[mb][nb][1]);
            if (r1 < C_DIM)
                *(float2*)&ob[(size_t)r1 * T_DIM + cc] =
                    make_float2(acc[mb][nb][2], acc[mb][nb][3]);
        }
    }
}

// Sample 2048 outputs, recompute fp32, flag if off (x3 error ~1e-6 rel).
__global__ void check_kernel(const float* __restrict__ x, const float* __restrict__ W,
                             const float* __restrict__ out) {
    const int i = blockIdx.x * blockDim.x + threadIdx.x;
    const int b = i & (BATCH - 1);
    const int c = (i * 37) % C_DIM;
    const int t = (i * 613) % T_DIM;
    const float* wr = W + ((size_t)g_sidx[b] * C_DIM + c) * C_DIM;
    const float* xc = x + (size_t)b * C_DIM * T_DIM + t;
    float acc = 0.f;
    for (int k = 0; k < C_DIM; k++) acc += wr[k] * xc[(size_t)k * T_DIM];
    const float got = out[((size_t)b * C_DIM + c) * T_DIM + t];
    if (fabsf(got - acc) > 3e-3f * fmaxf(fabsf(acc), 1.0f)) atomicExch(&g_flag, 1);
}

// Proven SIMT fallback (633us path); early-exits unless flagged.
__global__ __launch_bounds__(256)
void simt_gemm_kernel(const float* __restrict__ x, const float* __restrict__ W,
                      float* __restrict__ out) {
    if (!g_flag) return;
    __shared__ float As[64][17];
    __shared__ float Bs[16][64];
    const int b = blockIdx.z, oBase = blockIdx.y * 64, tBase = blockIdx.x * 64;
    const float* __restrict__ Wb = W + (size_t)g_sidx[b] * C_DIM * C_DIM;
    const float* __restrict__ xb = x + (size_t)b * C_DIM * T_DIM;
    float* __restrict__ ob = out + (size_t)b * C_DIM * T_DIM;
    const int tid = threadIdx.x, tx = tid & 15, ty = tid >> 4;
    const int aRow = tid >> 2, aCol = (tid & 3) * 4, bRow = tid >> 4, bCol = (tid & 15) * 4;
    const int oLoad = oBase + aRow;
    const bool aValid = (oLoad < C_DIM);
    const float* aPtr = Wb + (size_t)oLoad * C_DIM + aCol;
    const float* bPtr = xb + (size_t)bRow * T_DIM + tBase + bCol;
    float acc[4][4] = {};
    for (int k0 = 0; k0 < C_DIM; k0 += 16) {
        float4 av = aValid ? *(const float4*)(aPtr + k0) : make_float4(0.f,0.f,0.f,0.f);
        float4 bv = *(const float4*)(bPtr + (size_t)k0 * T_DIM);
        As[aRow][aCol+0]=av.x; As[aRow][aCol+1]=av.y; As[aRow][aCol+2]=av.z; As[aRow][aCol+3]=av.w;
        *(float4*)&Bs[bRow][bCol] = bv;
        __syncthreads();
#pragma unroll
        for (int k = 0; k < 16; k++) {
            const float a0=As[ty*4+0][k], a1=As[ty*4+1][k], a2=As[ty*4+2][k], a3=As[ty*4+3][k];
            const float4 bq = *(const float4*)&Bs[k][tx*4];
            acc[0][0]+=a0*bq.x; acc[0][1]+=a0*bq.y; acc[0][2]+=a0*bq.z; acc[0][3]+=a0*bq.w;
            acc[1][0]+=a1*bq.x; acc[1][1]+=a1*bq.y; acc[1][2]+=a1*bq.z; acc[1][3]+=a1*bq.w;
            acc[2][0]+=a2*bq.x; acc[2][1]+=a2*bq.y; acc[2][2]+=a2*bq.z; acc[2][3]+=a2*bq.w;
            acc[3][0]+=a3*bq.x; acc[3][1]+=a3*bq.y; acc[3][2]+=a3*bq.z; acc[3][3]+=a3*bq.w;
        }
        __syncthreads();
    }
#pragma unroll
    for (int i = 0; i < 4; i++) {
        const int oo = oBase + ty * 4 + i;
        if (oo < C_DIM)
            *(float4*)&ob[(size_t)oo * T_DIM + tBase + tx * 4] =
                make_float4(acc[i][0], acc[i][1], acc[i][2], acc[i][3]);
    }
}

extern "C" void kernel_launch(void* const* d_in, const int* in_sizes, int n_in,
                              void* d_out, int out_size) {
    const float* x = (const float*)d_in[0];
    const int* idx = (const int*)d_in[1];
    const float* W = (const float*)d_in[2];
    float* out = (float*)d_out;

    decode_sidx_kernel<<<1, 128>>>(idx);
    dim3 grid(T_DIM / NT, (C_DIM + MT - 1) / MT, BATCH);   // (4, 5, 128)
    mma_gemm_kernel<<<grid, 256>>>(x, W, out);
    check_kernel<<<16, 128>>>(x, W, out);
    dim3 fgrid(16, 5, BATCH);
    simt_gemm_kernel<<<fgrid, 256>>>(x, W, out);
}

// round 9
// speedup vs baseline: 2.9162x; 1.5521x over previous
#include <cuda_runtime.h>
#include <cuda_bf16.h>
#include <cstdint>

#define C_DIM 272
#define T_DIM 1024
#define BATCH 128
#define MT 64
#define NT 256
#define AP 72
#define TP 264

__device__ int g_sidx[BATCH];
__device__ int g_flag;   // 1 => mma result bad -> run SIMT fallback

__global__ void decode_sidx_kernel(const int* __restrict__ raw) {
    __shared__ int is_i32;
    if (threadIdx.x == 0) { is_i32 = 0; g_flag = 0; }
    __syncthreads();
    int t = threadIdx.x;
    if (t < 64 && raw[2 * t + 1] != 0) atomicExch(&is_i32, 1);
    __syncthreads();
    if (t < BATCH) g_sidx[t] = is_i32 ? raw[t] : raw[2 * t];
}

// pack two floats as bf16x2, low half = 'e' (even k), high half = 'o' (odd k)
__device__ __forceinline__ uint32_t pk(float e, float o) {
    __nv_bfloat162 p = __floats2bfloat162_rn(e, o);   // .x = e (low), .y = o
    return *reinterpret_cast<uint32_t*>(&p);
}
__device__ __forceinline__ void split2(float v, float& hi, float& lo) {
    const __nv_bfloat16 h = __float2bfloat16_rn(v);
    hi = __bfloat162float(h);
    lo = v - hi;
}
__device__ __forceinline__ void mma16(float* d, const uint32_t* a, uint32_t b0, uint32_t b1) {
    asm volatile("mma.sync.aligned.m16n8k16.row.col.f32.bf16.bf16.f32 "
        "{%0,%1,%2,%3}, {%4,%5,%6,%7}, {%8,%9}, {%0,%1,%2,%3};"
        : "+f"(d[0]), "+f"(d[1]), "+f"(d[2]), "+f"(d[3])
        : "r"(a[0]), "r"(a[1]), "r"(a[2]), "r"(a[3]), "r"(b0), "r"(b1));
}

// CTA: 64(chan) x 256(time); 8 warps (2x4), warp tile 32x64.
// bf16 x3 split, m16n8k16; smem holds packed bf16x2 limbs [kpair][c/t].
__global__ __launch_bounds__(256, 2)
void mma_gemm_kernel(const float* __restrict__ x, const float* __restrict__ W,
                     float* __restrict__ out) {
    __shared__ uint32_t Ah[8][AP], Al[8][AP];    // [kpair][chan]
    __shared__ uint32_t Bh[8][TP], Bl[8][TP];    // [kpair][time]

    const int b = blockIdx.z, oBase = blockIdx.y * MT, tBase = blockIdx.x * NT;
    const int s = g_sidx[b];
    const float* __restrict__ Wb = W + (size_t)s * C_DIM * C_DIM;
    const float* __restrict__ xb = x + (size_t)b * C_DIM * T_DIM;

    const int tid = threadIdx.x, lane = tid & 31, warp = tid >> 5;
    const int wm = (warp >> 2) * 32, wn = (warp & 3) * 64;
    const int fr = lane >> 2, fc = lane & 3;

    const int aC = tid & 63, aKq = (tid >> 6) * 4;   // 4 k's = kpairs aKq/2, +1
    const bool aV = (oBase + aC) < C_DIM;
    const float* aP = Wb + (size_t)(oBase + aC) * C_DIM + aKq;
    const float* bP = xb + tBase + tid;

    float acc[2][8][4];
#pragma unroll
    for (int mb = 0; mb < 2; mb++)
#pragma unroll
        for (int nb = 0; nb < 8; nb++)
#pragma unroll
            for (int j = 0; j < 4; j++) acc[mb][nb][j] = 0.0f;

    for (int k0 = 0; k0 < C_DIM; k0 += 16) {   // 272 = 17*16 exact
        // ---- stage A: 4 k's -> 2 packed kpairs per limb ----
        {
            const float4 av = aV ? *(const float4*)(aP + k0)
                                 : make_float4(0.f, 0.f, 0.f, 0.f);
            float h0, l0, h1, l1, h2, l2, h3, l3;
            split2(av.x, h0, l0); split2(av.y, h1, l1);
            split2(av.z, h2, l2); split2(av.w, h3, l3);
            const int kp = aKq >> 1;
            Ah[kp][aC]     = pk(h0, h1);  Al[kp][aC]     = pk(l0, l1);
            Ah[kp + 1][aC] = pk(h2, h3);  Al[kp + 1][aC] = pk(l2, l3);
        }
        // ---- stage B: 16 k's -> 8 packed kpairs per limb (no transpose) ----
#pragma unroll
        for (int j = 0; j < 8; j++) {
            const float v0 = bP[(size_t)(k0 + 2 * j) * T_DIM];
            const float v1 = bP[(size_t)(k0 + 2 * j + 1) * T_DIM];
            float h0, l0, h1, l1;
            split2(v0, h0, l0); split2(v1, h1, l1);
            Bh[j][tid] = pk(h0, h1);
            Bl[j][tid] = pk(l0, l1);
        }
        __syncthreads();

        // ---- fragments + mma (one k16 step per tile) ----
        uint32_t ah[2][4], al[2][4];
#pragma unroll
        for (int mb = 0; mb < 2; mb++) {
            const int m = wm + mb * 16 + fr;
            ah[mb][0] = Ah[fc][m];     ah[mb][1] = Ah[fc][m + 8];
            ah[mb][2] = Ah[fc + 4][m]; ah[mb][3] = Ah[fc + 4][m + 8];
            al[mb][0] = Al[fc][m];     al[mb][1] = Al[fc][m + 8];
            al[mb][2] = Al[fc + 4][m]; al[mb][3] = Al[fc + 4][m + 8];
        }
#pragma unroll
        for (int half = 0; half < 2; half++) {
            uint32_t bh[4][2], bl[4][2];
#pragma unroll
            for (int q = 0; q < 4; q++) {
                const int n = wn + (half * 4 + q) * 8 + fr;
                bh[q][0] = Bh[fc][n]; bh[q][1] = Bh[fc + 4][n];
                bl[q][0] = Bl[fc][n]; bl[q][1] = Bl[fc + 4][n];
            }
            // pass 1: Ahi*Bhi
#pragma unroll
            for (int q = 0; q < 4; q++) {
                mma16(acc[0][half * 4 + q], ah[0], bh[q][0], bh[q][1]);
                mma16(acc[1][half * 4 + q], ah[1], bh[q][0], bh[q][1]);
            }
            // pass 2: Alo*Bhi
#pragma unroll
            for (int q = 0; q < 4; q++) {
                mma16(acc[0][half * 4 + q], al[0], bh[q][0], bh[q][1]);
                mma16(acc[1][half * 4 + q], al[1], bh[q][0], bh[q][1]);
            }
            // pass 3: Ahi*Blo
#pragma unroll
            for (int q = 0; q < 4; q++) {
                mma16(acc[0][half * 4 + q], ah[0], bl[q][0], bl[q][1]);
                mma16(acc[1][half * 4 + q], ah[1], bl[q][0], bl[q][1]);
            }
        }
        __syncthreads();
    }

    float* __restrict__ ob = out + (size_t)b * C_DIM * T_DIM;
#pragma unroll
    for (int mb = 0; mb < 2; mb++) {
        const int r0 = oBase + wm + mb * 16 + fr;
        const int r1 = r0 + 8;
#pragma unroll
        for (int nb = 0; nb < 8; nb++) {
            const int cc = tBase + wn + nb * 8 + fc * 2;
            if (r0 < C_DIM)
                *(float2*)&ob[(size_t)r0 * T_DIM + cc] =
                    make_float2(acc[mb][nb][0], acc[mb][nb][1]);
            if (r1 < C_DIM)
                *(float2*)&ob[(size_t)r1 * T_DIM + cc] =
                    make_float2(acc[mb][nb][2], acc[mb][nb][3]);
        }
    }
}

// Sample 512 outputs, recompute fp32, flag if off by > 3e-3 rel.
__global__ void check_kernel(const float* __restrict__ x, const float* __restrict__ W,
                             const float* __restrict__ out) {
    const int i = blockIdx.x * blockDim.x + threadIdx.x;
    const int b = i & (BATCH - 1);
    const int c = (i * 37) % C_DIM;
    const int t = (i * 613) % T_DIM;
    const float* wr = W + ((size_t)g_sidx[b] * C_DIM + c) * C_DIM;
    const float* xc = x + (size_t)b * C_DIM * T_DIM + t;
    float acc = 0.f;
    for (int k = 0; k < C_DIM; k++) acc += wr[k] * xc[(size_t)k * T_DIM];
    const float got = out[((size_t)b * C_DIM + c) * T_DIM + t];
    if (fabsf(got - acc) > 3e-3f * fmaxf(fabsf(acc), 1.0f)) atomicExch(&g_flag, 1);
}

// Proven SIMT fallback; early-exits unless flagged.
__global__ __launch_bounds__(256)
void simt_gemm_kernel(const float* __restrict__ x, const float* __restrict__ W,
                      float* __restrict__ out) {
    if (!g_flag) return;
    __shared__ float As[64][17];
    __shared__ float Bs[16][64];
    const int b = blockIdx.z, oBase = blockIdx.y * 64, tBase = blockIdx.x * 64;
    const float* __restrict__ Wb = W + (size_t)g_sidx[b] * C_DIM * C_DIM;
    const float* __restrict__ xb = x + (size_t)b * C_DIM * T_DIM;
    float* __restrict__ ob = out + (size_t)b * C_DIM * T_DIM;
    const int tid = threadIdx.x, tx = tid & 15, ty = tid >> 4;
    const int aRow = tid >> 2, aCol = (tid & 3) * 4, bRow = tid >> 4, bCol = (tid & 15) * 4;
    const int oLoad = oBase + aRow;
    const bool aValid = (oLoad < C_DIM);
    const float* aPtr = Wb + (size_t)oLoad * C_DIM + aCol;
    const float* bPtr = xb + (size_t)bRow * T_DIM + tBase + bCol;
    float acc[4][4] = {};
    for (int k0 = 0; k0 < C_DIM; k0 += 16) {
        float4 av = aValid ? *(const float4*)(aPtr + k0) : make_float4(0.f,0.f,0.f,0.f);
        float4 bv = *(const float4*)(bPtr + (size_t)k0 * T_DIM);
        As[aRow][aCol+0]=av.x; As[aRow][aCol+1]=av.y; As[aRow][aCol+2]=av.z; As[aRow][aCol+3]=av.w;
        *(float4*)&Bs[bRow][bCol] = bv;
        __syncthreads();
#pragma unroll
        for (int k = 0; k < 16; k++) {
            const float a0=As[ty*4+0][k], a1=As[ty*4+1][k], a2=As[ty*4+2][k], a3=As[ty*4+3][k];
            const float4 bq = *(const float4*)&Bs[k][tx*4];
            acc[0][0]+=a0*bq.x; acc[0][1]+=a0*bq.y; acc[0][2]+=a0*bq.z; acc[0][3]+=a0*bq.w;
            acc[1][0]+=a1*bq.x; acc[1][1]+=a1*bq.y; acc[1][2]+=a1*bq.z; acc[1][3]+=a1*bq.w;
            acc[2][0]+=a2*bq.x; acc[2][1]+=a2*bq.y; acc[2][2]+=a2*bq.z; acc[2][3]+=a2*bq.w;
            acc[3][0]+=a3*bq.x; acc[3][1]+=a3*bq.y; acc[3][2]+=a3*bq.z; acc[3][3]+=a3*bq.w;
        }
        __syncthreads();
    }
#pragma unroll
    for (int i = 0; i < 4; i++) {
        const int oo = oBase + ty * 4 + i;
        if (oo < C_DIM)
            *(float4*)&ob[(size_t)oo * T_DIM + tBase + tx * 4] =
                make_float4(acc[i][0], acc[i][1], acc[i][2], acc[i][3]);
    }
}

extern "C" void kernel_launch(void* const* d_in, const int* in_sizes, int n_in,
                              void* d_out, int out_size) {
    const float* x = (const float*)d_in[0];
    const int* idx = (const int*)d_in[1];
    const float* W = (const float*)d_in[2];
    float* out = (float*)d_out;

    decode_sidx_kernel<<<1, 128>>>(idx);
    dim3 grid(T_DIM / NT, (C_DIM + MT - 1) / MT, BATCH);   // (4, 5, 128)
    mma_gemm_kernel<<<grid, 256>>>(x, W, out);
    check_kernel<<<4, 128>>>(x, W, out);
    dim3 fgrid(16, 5, BATCH);
    simt_gemm_kernel<<<fgrid, 256>>>(x, W, out);
}

// round 10
// speedup vs baseline: 3.8023x; 1.3038x over previous
#include <cuda_runtime.h>
#include <cuda_bf16.h>
#include <cstdint>

#define C_DIM 272
#define T_DIM 1024
#define BATCH 128
#define MT 64
#define NT 256
#define AP 72
#define TP 264

__device__ int g_sidx[BATCH];

__global__ void decode_sidx_kernel(const int* __restrict__ raw) {
    __shared__ int is_i32;
    if (threadIdx.x == 0) is_i32 = 0;
    __syncthreads();
    int t = threadIdx.x;
    if (t < 64 && raw[2 * t + 1] != 0) atomicExch(&is_i32, 1);
    __syncthreads();
    if (t < BATCH) g_sidx[t] = is_i32 ? raw[t] : raw[2 * t];
}

// pack two floats as bf16x2 (low = even k, high = odd k)
__device__ __forceinline__ uint32_t pk(float e, float o) {
    __nv_bfloat162 p = __floats2bfloat162_rn(e, o);
    return *reinterpret_cast<uint32_t*>(&p);
}
__device__ __forceinline__ void split2(float v, float& hi, float& lo) {
    const __nv_bfloat16 h = __float2bfloat16_rn(v);
    hi = __bfloat162float(h);
    lo = v - hi;
}
__device__ __forceinline__ void mma16(float* d, const uint32_t* a, uint32_t b0, uint32_t b1) {
    asm volatile("mma.sync.aligned.m16n8k16.row.col.f32.bf16.bf16.f32 "
        "{%0,%1,%2,%3}, {%4,%5,%6,%7}, {%8,%9}, {%0,%1,%2,%3};"
        : "+f"(d[0]), "+f"(d[1]), "+f"(d[2]), "+f"(d[3])
        : "r"(a[0]), "r"(a[1]), "r"(a[2]), "r"(a[3]), "r"(b0), "r"(b1));
}

// CTA: 64(chan) x 256(time); 8 warps (2x4), warp tile 32x64.
// bf16 x3 split, m16n8k16; register-pipelined staging.
__global__ __launch_bounds__(256, 2)
void mma_gemm_kernel(const float* __restrict__ x, const float* __restrict__ W,
                     float* __restrict__ out) {
    __shared__ uint32_t Ah[8][AP], Al[8][AP];    // [kpair][chan]
    __shared__ uint32_t Bh[8][TP], Bl[8][TP];    // [kpair][time]

    const int b = blockIdx.z, oBase = blockIdx.y * MT, tBase = blockIdx.x * NT;
    const int s = g_sidx[b];
    const float* __restrict__ Wb = W + (size_t)s * C_DIM * C_DIM;
    const float* __restrict__ xb = x + (size_t)b * C_DIM * T_DIM;

    const int tid = threadIdx.x, lane = tid & 31, warp = tid >> 5;
    const int wm = (warp >> 2) * 32, wn = (warp & 3) * 64;
    const int fr = lane >> 2, fc = lane & 3;

    const int aC = tid & 63, aKq = (tid >> 6) * 4;
    const bool aV = (oBase + aC) < C_DIM;
    const float* aP = Wb + (size_t)(oBase + aC) * C_DIM + aKq;
    const float* bP = xb + tBase + tid;

    float acc[2][8][4];
#pragma unroll
    for (int mb = 0; mb < 2; mb++)
#pragma unroll
        for (int nb = 0; nb < 8; nb++)
#pragma unroll
            for (int j = 0; j < 4; j++) acc[mb][nb][j] = 0.0f;

    // prologue: prefetch tile 0 into registers
    float4 aNxt = aV ? *(const float4*)(aP) : make_float4(0.f, 0.f, 0.f, 0.f);
    float bNxt[16];
#pragma unroll
    for (int j = 0; j < 16; j++) bNxt[j] = bP[(size_t)j * T_DIM];

    for (int ck = 0; ck < 17; ck++) {   // 272 = 17*16
        // ---- commit staged registers to smem (split bf16) ----
        {
            float h0, l0, h1, l1, h2, l2, h3, l3;
            split2(aNxt.x, h0, l0); split2(aNxt.y, h1, l1);
            split2(aNxt.z, h2, l2); split2(aNxt.w, h3, l3);
            const int kp = aKq >> 1;
            Ah[kp][aC]     = pk(h0, h1);  Al[kp][aC]     = pk(l0, l1);
            Ah[kp + 1][aC] = pk(h2, h3);  Al[kp + 1][aC] = pk(l2, l3);
        }
#pragma unroll
        for (int j = 0; j < 8; j++) {
            float h0, l0, h1, l1;
            split2(bNxt[2 * j], h0, l0); split2(bNxt[2 * j + 1], h1, l1);
            Bh[j][tid] = pk(h0, h1);
            Bl[j][tid] = pk(l0, l1);
        }
        __syncthreads();

        // ---- prefetch next tile (overlaps mma below) ----
        if (ck < 16) {
            const int kn = (ck + 1) * 16;
            aNxt = aV ? *(const float4*)(aP + kn) : make_float4(0.f, 0.f, 0.f, 0.f);
            const float* bPn = bP + (size_t)kn * T_DIM;
#pragma unroll
            for (int j = 0; j < 16; j++) bNxt[j] = bPn[(size_t)j * T_DIM];
        }

        // ---- fragments + mma (one k16 step per tile) ----
        uint32_t ah[2][4], al[2][4];
#pragma unroll
        for (int mb = 0; mb < 2; mb++) {
            const int m = wm + mb * 16 + fr;
            ah[mb][0] = Ah[fc][m];     ah[mb][1] = Ah[fc][m + 8];
            ah[mb][2] = Ah[fc + 4][m]; ah[mb][3] = Ah[fc + 4][m + 8];
            al[mb][0] = Al[fc][m];     al[mb][1] = Al[fc][m + 8];
            al[mb][2] = Al[fc + 4][m]; al[mb][3] = Al[fc + 4][m + 8];
        }
#pragma unroll
        for (int half = 0; half < 2; half++) {
            uint32_t bh[4][2], bl[4][2];
#pragma unroll
            for (int q = 0; q < 4; q++) {
                const int n = wn + (half * 4 + q) * 8 + fr;
                bh[q][0] = Bh[fc][n]; bh[q][1] = Bh[fc + 4][n];
                bl[q][0] = Bl[fc][n]; bl[q][1] = Bl[fc + 4][n];
            }
#pragma unroll
            for (int q = 0; q < 4; q++) {
                mma16(acc[0][half * 4 + q], ah[0], bh[q][0], bh[q][1]);
                mma16(acc[1][half * 4 + q], ah[1], bh[q][0], bh[q][1]);
            }
#pragma unroll
            for (int q = 0; q < 4; q++) {
                mma16(acc[0][half * 4 + q], al[0], bh[q][0], bh[q][1]);
                mma16(acc[1][half * 4 + q], al[1], bh[q][0], bh[q][1]);
            }
#pragma unroll
            for (int q = 0; q < 4; q++) {
                mma16(acc[0][half * 4 + q], ah[0], bl[q][0], bl[q][1]);
                mma16(acc[1][half * 4 + q], ah[1], bl[q][0], bl[q][1]);
            }
        }
        __syncthreads();
    }

    float* __restrict__ ob = out + (size_t)b * C_DIM * T_DIM;
#pragma unroll
    for (int mb = 0; mb < 2; mb++) {
        const int r0 = oBase + wm + mb * 16 + fr;
        const int r1 = r0 + 8;
#pragma unroll
        for (int nb = 0; nb < 8; nb++) {
            const int cc = tBase + wn + nb * 8 + fc * 2;
            if (r0 < C_DIM)
                *(float2*)&ob[(size_t)r0 * T_DIM + cc] =
                    make_float2(acc[mb][nb][0], acc[mb][nb][1]);
            if (r1 < C_DIM)
                *(float2*)&ob[(size_t)r1 * T_DIM + cc] =
                    make_float2(acc[mb][nb][2], acc[mb][nb][3]);
        }
    }
}

extern "C" void kernel_launch(void* const* d_in, const int* in_sizes, int n_in,
                              void* d_out, int out_size) {
    const float* x = (const float*)d_in[0];
    const int* idx = (const int*)d_in[1];
    const float* W = (const float*)d_in[2];
    float* out = (float*)d_out;

    decode_sidx_kernel<<<1, 128>>>(idx);
    dim3 grid(T_DIM / NT, (C_DIM + MT - 1) / MT, BATCH);   // (4, 5, 128)
    mma_gemm_kernel<<<grid, 256>>>(x, W, out);
}